// round 2
// baseline (speedup 1.0000x reference)
#include <cuda_runtime.h>
#include <cuda_bf16.h>

// Problem constants (from reference): N=100000 nodes, E=1600000 edges, D=64.
#define MAXN 100000
#define MAXE 1600000
#define DD   64

// Scratch (device globals — no allocations allowed).
__device__ float g_deg[MAXN];            // degree, then overwritten with deg^-1/2
__device__ float g_agg[(size_t)MAXN * DD]; // aggregated messages (25.6 MB, L2-resident)

// ---------------------------------------------------------------------------
// K1: deg[i] = 1 (self loop)
__global__ void k_init_deg(int n) {
    int i = blockIdx.x * blockDim.x + threadIdx.x;
    if (i < n) g_deg[i] = 1.0f;
}

// K2: deg[dst] += 1 per edge
__global__ void k_count(const int* __restrict__ ei, int E) {
    int e = blockIdx.x * blockDim.x + threadIdx.x;
    if (e < E) atomicAdd(&g_deg[ei[E + e]], 1.0f);
}

// K3: deg -> rsqrt(deg) in place
__global__ void k_dinv(int n) {
    int i = blockIdx.x * blockDim.x + threadIdx.x;
    if (i < n) g_deg[i] = rsqrtf(g_deg[i]);
}

// K4: agg[i,:] = x[i,:] * dinv[i]^2   (self-loop contribution, coalesced float4)
__global__ void k_selfinit(const float4* __restrict__ x4, int n) {
    int idx = blockIdx.x * blockDim.x + threadIdx.x;   // over n*16 float4 chunks
    if (idx >= n * (DD / 4)) return;
    int i = idx >> 4;
    float d = g_deg[i];
    float s = d * d;
    float4 v = x4[idx];
    v.x *= s; v.y *= s; v.z *= s; v.w *= s;
    reinterpret_cast<float4*>(g_agg)[idx] = v;
}

// K5: edge scatter. 16 threads per edge, each handles one float4 chunk.
// agg[dst,:] += x[src,:] * (dinv[src]*dinv[dst])  via vectorized red.global.add.v4
__global__ void k_scatter(const float4* __restrict__ x4,
                          const int* __restrict__ ei, int E) {
    long long idx = (long long)blockIdx.x * blockDim.x + threadIdx.x;
    if (idx >= (long long)E * (DD / 4)) return;
    int e = (int)(idx >> 4);
    int c = (int)(idx & 15);
    int s  = __ldg(&ei[e]);
    int dt = __ldg(&ei[E + e]);
    float nrm = __ldg(&g_deg[s]) * __ldg(&g_deg[dt]);
    float4 v = __ldg(&x4[(size_t)s * (DD / 4) + c]);
    v.x *= nrm; v.y *= nrm; v.z *= nrm; v.w *= nrm;
    float* dst = &g_agg[(size_t)dt * DD + c * 4];
#if __CUDA_ARCH__ >= 900
    asm volatile("red.global.add.v4.f32 [%0], {%1, %2, %3, %4};"
                 :: "l"(dst), "f"(v.x), "f"(v.y), "f"(v.z), "f"(v.w)
                 : "memory");
#else
    atomicAdd(dst + 0, v.x);
    atomicAdd(dst + 1, v.y);
    atomicAdd(dst + 2, v.z);
    atomicAdd(dst + 3, v.w);
#endif
}

// K6: out = agg @ W^T + b.  W[j,k] row-major; sW[k*64+j] = W[j*64+k].
// One node per thread, 16 float4 accumulators (64 outputs).
__global__ void k_gemm(const float* __restrict__ W,
                       const float* __restrict__ b,
                       float* __restrict__ out, int n) {
    __shared__ float sW[DD * DD];  // 16 KB, transposed: sW[k][j]
    for (int idx = threadIdx.x; idx < DD * DD; idx += blockDim.x) {
        int j = idx >> 6, k = idx & 63;
        sW[k * DD + j] = W[idx];
    }
    __syncthreads();

    int node = blockIdx.x * blockDim.x + threadIdx.x;
    if (node >= n) return;

    float4 acc[16];
    const float4* b4 = reinterpret_cast<const float4*>(b);
#pragma unroll
    for (int jj = 0; jj < 16; jj++) acc[jj] = __ldg(&b4[jj]);

    const float4* a4 = reinterpret_cast<const float4*>(g_agg) + (size_t)node * (DD / 4);
#pragma unroll
    for (int kk = 0; kk < 16; kk++) {
        float4 av = a4[kk];
#pragma unroll
        for (int s = 0; s < 4; s++) {
            float v = (s == 0) ? av.x : (s == 1) ? av.y : (s == 2) ? av.z : av.w;
            const float4* wr = reinterpret_cast<const float4*>(&sW[(kk * 4 + s) * DD]);
#pragma unroll
            for (int jj = 0; jj < 16; jj++) {
                float4 w = wr[jj];
                acc[jj].x += v * w.x;
                acc[jj].y += v * w.y;
                acc[jj].z += v * w.z;
                acc[jj].w += v * w.w;
            }
        }
    }

    float4* o4 = reinterpret_cast<float4*>(out) + (size_t)node * (DD / 4);
#pragma unroll
    for (int jj = 0; jj < 16; jj++) o4[jj] = acc[jj];
}

// ---------------------------------------------------------------------------
extern "C" void kernel_launch(void* const* d_in, const int* in_sizes, int n_in,
                              void* d_out, int out_size) {
    const float* x  = (const float*)d_in[0];
    const int*   ei = (const int*)d_in[1];
    const float* W  = (const float*)d_in[2];
    const float* b  = (const float*)d_in[3];
    float* out = (float*)d_out;

    int D = in_sizes[3];            // 64
    int n = in_sizes[0] / D;        // 100000
    int E = in_sizes[1] / 2;        // 1600000

    const int T = 256;
    k_init_deg<<<(n + T - 1) / T, T>>>(n);
    k_count<<<(E + T - 1) / T, T>>>(ei, E);
    k_dinv<<<(n + T - 1) / T, T>>>(n);

    int self_work = n * (D / 4);
    k_selfinit<<<(self_work + T - 1) / T, T>>>((const float4*)x, n);

    long long scat_work = (long long)E * (D / 4);
    int scat_blocks = (int)((scat_work + T - 1) / T);
    k_scatter<<<scat_blocks, T>>>((const float4*)x, ei, E);

    k_gemm<<<(n + T - 1) / T, T>>>(W, b, out, n);
}